// round 8
// baseline (speedup 1.0000x reference)
#include <cuda_runtime.h>
#include <cuda_fp16.h>
#include <cstdint>
#include <cstddef>

#define NUMNODES 32768
#define NCHAIN   1024

// -------- global scratch (no allocations allowed) --------
__device__ __half g_ymsg[(size_t)NUMNODES * 1024];   // 64 MB msg buffer (fp16)
__device__ float  g_yself[(size_t)NUMNODES * 128];   // 16 MB self buffer (fp32)
__device__ float  g_alpha[(size_t)NUMNODES * 16];
__device__ float  g_bufA[(size_t)NUMNODES * 128];
__device__ float  g_bufB[(size_t)NUMNODES * 128];
__device__ __half g_xh[(size_t)NUMNODES * 128];      // split activations (fp16)
__device__ __half g_xl[(size_t)NUMNODES * 128];
#define WSLOT (1152 * 128)
__device__ __half g_w16[3 * WSLOT];                  // single fp16 weights [n][k]
__device__ float g_bias[3 * 1152];

// ================= PTX helpers (baseline ISA only) =================
__device__ __forceinline__ uint32_t smem_u32(const void* p) {
    uint32_t a;
    asm("{ .reg .u64 t; cvta.to.shared.u64 t, %1; cvt.u32.u64 %0, t; }" : "=r"(a) : "l"(p));
    return a;
}
__device__ __forceinline__ void cp16(uint32_t dst, const void* src) {
    asm volatile("{ .reg .u64 g; cvta.to.global.u64 g, %1; cp.async.cg.shared.global [%0], [g], 16; }"
        :: "r"(dst), "l"(src) : "memory");
}
__device__ __forceinline__ void cp_commit_wait() {
    asm volatile("cp.async.commit_group;" ::: "memory");
    asm volatile("cp.async.wait_group 0;" ::: "memory");
}
__device__ __forceinline__ void ldm_x4(uint32_t* r, uint32_t addr) {
    asm volatile("ldmatrix.sync.aligned.m8n8.x4.shared.b16 {%0,%1,%2,%3}, [%4];"
        : "=r"(r[0]), "=r"(r[1]), "=r"(r[2]), "=r"(r[3]) : "r"(addr));
}
__device__ __forceinline__ void mma_f16(float* d, const uint32_t* a, const uint32_t* b) {
    asm volatile(
        "mma.sync.aligned.m16n8k16.row.col.f32.f16.f16.f32 "
        "{%0,%1,%2,%3}, {%4,%5,%6,%7}, {%8,%9}, {%0,%1,%2,%3};"
        : "+f"(d[0]), "+f"(d[1]), "+f"(d[2]), "+f"(d[3])
        : "r"(a[0]), "r"(a[1]), "r"(a[2]), "r"(a[3]), "r"(b[0]), "r"(b[1]));
}
__device__ __forceinline__ float leaky(float v) { return (v > 0.f) ? v : 0.01f * v; }

// ================= combined weight convert (all 3 MMA layers) =================
__global__ __launch_bounds__(256) void convert_w_all(
    const float* __restrict__ Wm2, const float* __restrict__ bm2,
    const float* __restrict__ Ws2, const float* __restrict__ bs2,
    const float* __restrict__ Wm3, const float* __restrict__ bm3,
    const float* __restrict__ Ws3, const float* __restrict__ bs3,
    const float* __restrict__ Wm4, const float* __restrict__ bm4,
    const float* __restrict__ Ws4, const float* __restrict__ bs4,
    __half* __restrict__ w16, float* __restrict__ bias)
{
    int idx = blockIdx.x * 256 + threadIdx.x;
    int layer, K, COUT;
    const float *Wm, *bm, *Ws, *bs;
    if (idx < 1152 * 128) {
        layer = 0; K = 128; COUT = 128; Wm = Wm2; bm = bm2; Ws = Ws2; bs = bs2;
    } else if (idx < 2 * 1152 * 128) {
        idx -= 1152 * 128;
        layer = 1; K = 128; COUT = 64; Wm = Wm3; bm = bm3; Ws = Ws3; bs = bs3;
    } else if (idx < 2 * 1152 * 128 + 1152 * 64) {
        idx -= 2 * 1152 * 128;
        layer = 2; K = 64; COUT = 64; Wm = Wm4; bm = bm4; Ws = Ws4; bs = bs4;
    } else return;

    const int n = idx / K, k = idx % K;
    float v;
    if (n < 1024)             v = Wm[(size_t)k * 1024 + n];
    else if (n < 1024 + COUT) v = Ws[(size_t)k * COUT + (n - 1024)];
    else                      v = 0.f;
    w16[(size_t)layer * WSLOT + idx] = __float2half(v);
    if (k == 0)
        bias[layer * 1152 + n] = (n < 1024) ? bm[n] : ((n < 1024 + COUT) ? bs[n - 1024] : 0.f);
}

// ================= layer 1: alpha =================
__global__ __launch_bounds__(256) void alpha1(
    const float* __restrict__ x, const float* __restrict__ Wm,
    const float* __restrict__ bm, const float* __restrict__ att)
{
    __shared__ float wm_s[1024], bm_s[1024], att_s[1024];
    const int tid = threadIdx.x;
    for (int i = tid; i < 1024; i += 256) {
        wm_s[i] = Wm[i]; bm_s[i] = bm[i]; att_s[i] = att[i];
    }
    __syncthreads();

    const int w = tid >> 5, l = tid & 31;
    const int g = blockIdx.x * 32 + l;
    const float xv = x[g];
    const int base = w * 128;
    float a = 0.f;
    #pragma unroll 8
    for (int c = 0; c < 128; c++) {
        const float t = leaky(fmaf(xv, wm_s[base + c], bm_s[base + c]));
        a = fmaf(t, att_s[base + c], a);
    }
    g_alpha[(size_t)g * 8 + w] = a;
}

// ================= layer 1: output (agg + self + ELU + split fp16) =================
__global__ __launch_bounds__(256) void out1(
    const float* __restrict__ x,  const float* __restrict__ Wm,
    const float* __restrict__ bm, const float* __restrict__ Ws,
    const float* __restrict__ bs,
    __half* __restrict__ xh, __half* __restrict__ xl)
{
    constexpr int NPB = 32;
    __shared__ float wm_s[1024], bm_s[1024];
    __shared__ float ws_s[128], bs_s[128];
    __shared__ float wgt[NPB][16];
    __shared__ float xs[NPB + 2];

    const int tid = threadIdx.x;
    const int gBase = blockIdx.x * NPB;

    for (int i = tid; i < 1024; i += 256) { wm_s[i] = Wm[i]; bm_s[i] = bm[i]; }
    if (tid < 128) { ws_s[tid] = Ws[tid]; bs_s[tid] = bs[tid]; }
    if (tid < NPB + 2) {
        int gi = gBase + tid - 1;
        gi = (gi < 0) ? 0 : ((gi > NUMNODES - 1) ? NUMNODES - 1 : gi);
        xs[tid] = x[gi];
    }
    {
        const int node = tid >> 3, h = tid & 7;
        const int g = gBase + node;
        const int nch = g & (NCHAIN - 1);
        float el, er;
        if (nch == 0)               { el = 0.f; er = 1.f; }
        else if (nch == NCHAIN - 1) { el = 1.f; er = 0.f; }
        else {
            const float al = g_alpha[(size_t)(g - 1) * 8 + h];
            const float ar = g_alpha[(size_t)(g + 1) * 8 + h];
            const float mx = fmaxf(al, ar);
            el = expf(al - mx); er = expf(ar - mx);
        }
        const float inv = (1.f / ((el + er) + 1e-16f)) * 0.125f;
        wgt[node][h]     = el * inv;
        wgt[node][8 + h] = er * inv;
    }
    __syncthreads();

    const int col = tid & 127;
    float wmv[8], bmv[8];
    #pragma unroll
    for (int h = 0; h < 8; h++) { wmv[h] = wm_s[h * 128 + col]; bmv[h] = bm_s[h * 128 + col]; }
    const float wsc = ws_s[col], bsc = bs_s[col];

    for (int n = (tid >> 7); n < NPB; n += 2) {
        const int g = gBase + n;
        const float xL = xs[n], xS = xs[n + 1], xR = xs[n + 2];
        float s = fmaf(xS, wsc, bsc);
        #pragma unroll
        for (int h = 0; h < 8; h++) {
            const float tL = leaky(fmaf(xL, wmv[h], bmv[h]));
            const float tR = leaky(fmaf(xR, wmv[h], bmv[h]));
            s = fmaf(wgt[n][h], tL, s);
            s = fmaf(wgt[n][8 + h], tR, s);
        }
        s = (s > 0.f) ? s : expm1f(s);           // ELU
        const __half hv = __float2half(s);
        xh[(size_t)g * 128 + col] = hv;
        xl[(size_t)g * 128 + col] = __float2half(s - __half2float(hv));
    }
}

// ================= mma.sync fused GEMM (layers 2-4), 2-pass exact-A =================
// 4 warps (2M x 2N), warp tile 32m x 64n. B via ldmatrix.x4 pairs.
// D = xh*w + xl*w. Tile 64m x 128n per block.
template<int K, int C>
__global__ __launch_bounds__(128, 3) void gemm_mma(
    const __half* __restrict__ xh, const __half* __restrict__ xl,
    const __half* __restrict__ w16,
    const float* __restrict__ bias, const float* __restrict__ att,
    __half* __restrict__ ymsg, float* __restrict__ yself)
{
    constexpr int SROW = K + 8;
    extern __shared__ __align__(16) char smem[];
    __half* sAh = reinterpret_cast<__half*>(smem);
    __half* sAl = sAh + 64 * SROW;
    __half* sB  = sAl + 64 * SROW;
    float* alpha_s = reinterpret_cast<float*>(sB + 128 * SROW);   // [2][64]

    const int tid  = threadIdx.x;
    const int lane = tid & 31;
    const int wid  = tid >> 5;
    const int warpM = wid >> 1;          // 0..1
    const int warpN = wid & 1;           // 0..1
    const int g = lane >> 2, t = lane & 3;

    const int mBase = blockIdx.x * 64;
    const int nBase = blockIdx.y * 128;
    const bool isMsg = (nBase < 1024);

    // ---- cp.async cooperative loads ----
    {
        constexpr int VPR = K / 8;
        const uint32_t uAh = smem_u32(sAh), uAl = smem_u32(sAl);
        const uint32_t uB = smem_u32(sB);
        const uint4* gAh = reinterpret_cast<const uint4*>(xh + (size_t)mBase * K);
        const uint4* gAl = reinterpret_cast<const uint4*>(xl + (size_t)mBase * K);
        const uint4* gB  = reinterpret_cast<const uint4*>(w16 + (size_t)nBase * K);
        #pragma unroll
        for (int i = 0; i < (64 * VPR) / 128; i++) {
            const int idx = tid + i * 128;
            const int row = idx / VPR, kv = idx % VPR;
            const uint32_t so = (row * (SROW / 8) + kv) * 16;
            cp16(uAh + so, gAh + idx);
            cp16(uAl + so, gAl + idx);
        }
        #pragma unroll
        for (int i = 0; i < (128 * VPR) / 128; i++) {
            const int idx = tid + i * 128;
            const int row = idx / VPR, kv = idx % VPR;
            const uint32_t so = (row * (SROW / 8) + kv) * 16;
            cp16(uB + so, gB + idx);
        }
        cp_commit_wait();
    }
    __syncthreads();

    // ---- MMA mainloop ----
    float acc[2][8][4];
    #pragma unroll
    for (int mi = 0; mi < 2; mi++)
        #pragma unroll
        for (int ni = 0; ni < 8; ni++)
            #pragma unroll
            for (int e = 0; e < 4; e++) acc[mi][ni][e] = 0.f;

    const uint32_t uAh = smem_u32(sAh), uAl = smem_u32(sAl);
    const uint32_t uB = smem_u32(sB);
    const uint32_t aOfs = ((warpM * 32 + (lane & 15)) * SROW + ((lane >> 4) << 3)) * 2;
    // B x4: lanes 0-7 -> (tile 2p, k+0), 8-15 -> (tile 2p, k+8),
    //       16-23 -> (tile 2p+1, k+0), 24-31 -> (tile 2p+1, k+8)
    const uint32_t bOfs = ((warpN * 64 + ((lane >> 4) << 3) + (lane & 7)) * SROW
                          + (((lane >> 3) & 1) << 3)) * 2;

    #pragma unroll
    for (int kc = 0; kc < K / 16; kc++) {
        const uint32_t kByte = kc * 32;
        uint32_t ah[2][4], al[2][4];
        #pragma unroll
        for (int mi = 0; mi < 2; mi++) {
            const uint32_t ro = aOfs + mi * (16 * SROW * 2) + kByte;
            ldm_x4(ah[mi], uAh + ro);
            ldm_x4(al[mi], uAl + ro);
        }
        uint32_t bw[8][2];
        #pragma unroll
        for (int p = 0; p < 4; p++) {
            uint32_t r[4];
            ldm_x4(r, uB + bOfs + p * (16 * SROW * 2) + kByte);
            bw[2 * p][0] = r[0];     bw[2 * p][1] = r[1];
            bw[2 * p + 1][0] = r[2]; bw[2 * p + 1][1] = r[3];
        }
        #pragma unroll
        for (int ni = 0; ni < 8; ni++) {
            #pragma unroll
            for (int mi = 0; mi < 2; mi++) {
                mma_f16(acc[mi][ni], ah[mi], bw[ni]);
                mma_f16(acc[mi][ni], al[mi], bw[ni]);
            }
        }
    }

    // ---- epilogue ----
    float alphaLoc[2][2] = {{0.f, 0.f}, {0.f, 0.f}};

    #pragma unroll
    for (int ni = 0; ni < 8; ni++) {
        const int n0 = nBase + warpN * 64 + ni * 8 + 2 * t;
        const float2 bb = *reinterpret_cast<const float2*>(&bias[n0]);
        float2 aa = make_float2(0.f, 0.f);
        if (isMsg) aa = *reinterpret_cast<const float2*>(&att[n0]);
        #pragma unroll
        for (int mi = 0; mi < 2; mi++) {
            float v0 = acc[mi][ni][0] + bb.x;
            float v1 = acc[mi][ni][1] + bb.y;
            float v2 = acc[mi][ni][2] + bb.x;
            float v3 = acc[mi][ni][3] + bb.y;
            const int row0 = mBase + warpM * 32 + mi * 16 + g;
            if (isMsg) {
                v0 = leaky(v0); v1 = leaky(v1); v2 = leaky(v2); v3 = leaky(v3);
                alphaLoc[mi][0] = fmaf(v0, aa.x, fmaf(v1, aa.y, alphaLoc[mi][0]));
                alphaLoc[mi][1] = fmaf(v2, aa.x, fmaf(v3, aa.y, alphaLoc[mi][1]));
                *reinterpret_cast<__half2*>(ymsg + (size_t)row0 * 1024 + n0) =
                    __floats2half2_rn(v0, v1);
                *reinterpret_cast<__half2*>(ymsg + (size_t)(row0 + 8) * 1024 + n0) =
                    __floats2half2_rn(v2, v3);
            } else {
                const int c = n0 - 1024;
                *reinterpret_cast<float2*>(yself + (size_t)row0 * 128 + c) = make_float2(v0, v1);
                *reinterpret_cast<float2*>(yself + (size_t)(row0 + 8) * 128 + c) = make_float2(v2, v3);
            }
        }
    }

    if (isMsg) {
        #pragma unroll
        for (int mi = 0; mi < 2; mi++)
            #pragma unroll
            for (int rh = 0; rh < 2; rh++) {
                float s = alphaLoc[mi][rh];
                s += __shfl_xor_sync(0xffffffffu, s, 1);
                s += __shfl_xor_sync(0xffffffffu, s, 2);
                alphaLoc[mi][rh] = s;
            }
        if (C == 64) {
            // one head per warp's 64-col span
            const int h = blockIdx.y * 2 + warpN;
            if (t == 0) {
                #pragma unroll
                for (int mi = 0; mi < 2; mi++) {
                    const int row0 = mBase + warpM * 32 + mi * 16 + g;
                    g_alpha[(size_t)row0 * 16 + h]       = alphaLoc[mi][0];
                    g_alpha[(size_t)(row0 + 8) * 16 + h] = alphaLoc[mi][1];
                }
            }
        } else {
            // C==128: combine the two N-warps via smem
            if (t == 0) {
                #pragma unroll
                for (int mi = 0; mi < 2; mi++) {
                    const int lr = warpM * 32 + mi * 16 + g;
                    alpha_s[warpN * 64 + lr]     = alphaLoc[mi][0];
                    alpha_s[warpN * 64 + lr + 8] = alphaLoc[mi][1];
                }
            }
            __syncthreads();
            if (tid < 64)
                g_alpha[(size_t)(mBase + tid) * 8 + blockIdx.y] =
                    alpha_s[tid] + alpha_s[64 + tid];
        }
    }
}

// ================= aggregation stencil (fp16 msg + fp32 self) =================
template<int C, int H, bool ELU, bool SPLIT, bool WF32>
__global__ __launch_bounds__(256) void agg2h(
    const __half* __restrict__ ymsg, const float* __restrict__ yself,
    float* __restrict__ xout,
    __half* __restrict__ xh, __half* __restrict__ xl)
{
    constexpr int TPN = C / 4;
    constexpr int NPB = 256 / TPN;

    __shared__ float wl_s[NPB * H];
    __shared__ float wr_s[NPB * H];

    const int tid = threadIdx.x;
    const int gBase = blockIdx.x * NPB;

    if (tid < NPB * H) {
        const int node = tid / H, h = tid % H;
        const int g = gBase + node;
        const int nch = g & (NCHAIN - 1);
        float el, er;
        if (nch == 0)               { el = 0.f; er = 1.f; }
        else if (nch == NCHAIN - 1) { el = 1.f; er = 0.f; }
        else {
            const float al = g_alpha[(size_t)(g - 1) * H + h];
            const float ar = g_alpha[(size_t)(g + 1) * H + h];
            const float mx = fmaxf(al, ar);
            el = expf(al - mx); er = expf(ar - mx);
        }
        const float inv = (1.f / ((el + er) + 1e-16f)) * (1.f / H);
        wl_s[tid] = el * inv;
        wr_s[tid] = er * inv;
    }
    __syncthreads();

    const int lane = tid % TPN, node = tid / TPN;
    const int g = gBase + node;
    const int nch = g & (NCHAIN - 1);
    const __half* rowL = ymsg + (size_t)((nch > 0)          ? g - 1 : g) * 1024;
    const __half* rowR = ymsg + (size_t)((nch < NCHAIN - 1) ? g + 1 : g) * 1024;
    const int c4 = lane * 4;

    float4 acc = make_float4(0.f, 0.f, 0.f, 0.f);
    #pragma unroll
    for (int h = 0; h < H; h++) {
        const float wl = wl_s[node * H + h];
        const float wr = wr_s[node * H + h];
        const uint2 uL = *reinterpret_cast<const uint2*>(rowL + h * C + c4);
        const uint2 uR = *reinterpret_cast<const uint2*>(rowR + h * C + c4);
        const float2 l0 = __half22float2(*reinterpret_cast<const __half2*>(&uL.x));
        const float2 l1 = __half22float2(*reinterpret_cast<const __half2*>(&uL.y));
        const float2 r0 = __half22float2(*reinterpret_cast<const __half2*>(&uR.x));
        const float2 r1 = __half22float2(*reinterpret_cast<const __half2*>(&uR.y));
        acc.x = fmaf(wl, l0.x, fmaf(wr, r0.x, acc.x));
        acc.y = fmaf(wl, l0.y, fmaf(wr, r0.y, acc.y));
        acc.z = fmaf(wl, l1.x, fmaf(wr, r1.x, acc.z));
        acc.w = fmaf(wl, l1.y, fmaf(wr, r1.y, acc.w));
    }
    const float4 sv = *reinterpret_cast<const float4*>(yself + (size_t)g * 128 + c4);
    acc.x += sv.x; acc.y += sv.y; acc.z += sv.z; acc.w += sv.w;
    if (ELU) {
        acc.x = (acc.x > 0.f) ? acc.x : expm1f(acc.x);
        acc.y = (acc.y > 0.f) ? acc.y : expm1f(acc.y);
        acc.z = (acc.z > 0.f) ? acc.z : expm1f(acc.z);
        acc.w = (acc.w > 0.f) ? acc.w : expm1f(acc.w);
    }
    if (WF32)
        *reinterpret_cast<float4*>(xout + (size_t)g * C + c4) = acc;
    if (SPLIT) {
        const float vv[4] = {acc.x, acc.y, acc.z, acc.w};
        __half hv[4], lv[4];
        #pragma unroll
        for (int e = 0; e < 4; e++) {
            hv[e] = __float2half(vv[e]);
            lv[e] = __float2half(vv[e] - __half2float(hv[e]));
        }
        *reinterpret_cast<uint2*>(xh + (size_t)g * C + c4) = *reinterpret_cast<uint2*>(hv);
        *reinterpret_cast<uint2*>(xl + (size_t)g * C + c4) = *reinterpret_cast<uint2*>(lv);
    }
}

// ================= layer 5 msg+self (fp32, small) =================
__global__ __launch_bounds__(256) void msg5(
    const float* __restrict__ x,  const float* __restrict__ Wm,
    const float* __restrict__ bm, const float* __restrict__ Ws,
    const float* __restrict__ bs, const float* __restrict__ att,
    float* __restrict__ y)
{
    __shared__ float wm_s[64 * 32];
    __shared__ float ws_s[64 * 32];
    __shared__ float x_s[8 * 64];

    const int tid = threadIdx.x;
    const int n = tid >> 5, o = tid & 31;
    const int gBase = blockIdx.x * 8;

    for (int i = tid; i < 64 * 32; i += 256) { wm_s[i] = Wm[i]; ws_s[i] = Ws[i]; }
    for (int i = tid; i < 8 * 64; i += 256)  x_s[i] = x[(size_t)gBase * 64 + i];
    __syncthreads();

    float am = __ldg(&bm[o]);
    float as = __ldg(&bs[o]);
    #pragma unroll
    for (int k = 0; k < 64; k++) {
        const float xv = x_s[n * 64 + k];
        am = fmaf(xv, wm_s[k * 32 + o], am);
        as = fmaf(xv, ws_s[k * 32 + o], as);
    }
    am = leaky(am);
    const int gg = gBase + n;
    y[(size_t)gg * 64 + o]      = am;
    y[(size_t)gg * 64 + 32 + o] = as;

    float a = am * __ldg(&att[o]);
    #pragma unroll
    for (int off = 16; off > 0; off >>= 1)
        a += __shfl_xor_sync(0xffffffffu, a, off);
    if (o == 0) g_alpha[gg] = a;
}

// fp32 agg for layer 5 (C=32, H=1, stride 64)
__global__ __launch_bounds__(256) void agg5(
    const float* __restrict__ y, float* __restrict__ xout)
{
    constexpr int TPN = 8, NPB = 32;
    __shared__ float wl_s[NPB], wr_s[NPB];
    const int tid = threadIdx.x;
    const int gBase = blockIdx.x * NPB;

    if (tid < NPB) {
        const int g = gBase + tid;
        const int nch = g & (NCHAIN - 1);
        float el, er;
        if (nch == 0)               { el = 0.f; er = 1.f; }
        else if (nch == NCHAIN - 1) { el = 1.f; er = 0.f; }
        else {
            const float al = g_alpha[(size_t)(g - 1)];
            const float ar = g_alpha[(size_t)(g + 1)];
            const float mx = fmaxf(al, ar);
            el = expf(al - mx); er = expf(ar - mx);
        }
        const float inv = 1.f / ((el + er) + 1e-16f);
        wl_s[tid] = el * inv;
        wr_s[tid] = er * inv;
    }
    __syncthreads();

    const int lane = tid % TPN, node = tid / TPN;
    const int g = gBase + node;
    const int nch = g & (NCHAIN - 1);
    const float* rowL = y + (size_t)((nch > 0)          ? g - 1 : g) * 64;
    const float* rowR = y + (size_t)((nch < NCHAIN - 1) ? g + 1 : g) * 64;
    const int c4 = lane * 4;
    const float wl = wl_s[node], wr = wr_s[node];
    const float4 mL = *reinterpret_cast<const float4*>(rowL + c4);
    const float4 mR = *reinterpret_cast<const float4*>(rowR + c4);
    const float4 sv = *reinterpret_cast<const float4*>(y + (size_t)g * 64 + 32 + c4);
    float4 acc;
    acc.x = fmaf(wl, mL.x, fmaf(wr, mR.x, sv.x));
    acc.y = fmaf(wl, mL.y, fmaf(wr, mR.y, sv.y));
    acc.z = fmaf(wl, mL.z, fmaf(wr, mR.z, sv.z));
    acc.w = fmaf(wl, mL.w, fmaf(wr, mR.w, sv.w));
    *reinterpret_cast<float4*>(xout + (size_t)g * 32 + c4) = acc;
}

// ================= readout =================
__global__ __launch_bounds__(1024) void final_k(
    const float* __restrict__ x5, const float* __restrict__ Wc,
    const float* __restrict__ bc, float* __restrict__ out, int out_size)
{
    const int tid = threadIdx.x;
    const int b = tid >> 5;
    const int c = tid & 31;
    const float v = x5[((size_t)b * NCHAIN + (NCHAIN - 1)) * 32 + c];
    if (32 + tid < out_size) out[32 + tid] = v;
    float p = v * __ldg(&Wc[c]);
    #pragma unroll
    for (int off = 16; off > 0; off >>= 1)
        p += __shfl_down_sync(0xffffffffu, p, off);
    if (c == 0 && b < out_size) out[b] = p + __ldg(&bc[0]);
}

// ================= launch =================
extern "C" void kernel_launch(void* const* d_in, const int* in_sizes, int n_in,
                              void* d_out, int out_size)
{
    const float* nodes = (const float*)d_in[0];
    const float* Wm1 = (const float*)d_in[1];  const float* bm1 = (const float*)d_in[2];
    const float* Ws1 = (const float*)d_in[3];  const float* bs1 = (const float*)d_in[4];
    const float* att1 = (const float*)d_in[5];
    const float* Wm2 = (const float*)d_in[6];  const float* bm2 = (const float*)d_in[7];
    const float* Ws2 = (const float*)d_in[8];  const float* bs2 = (const float*)d_in[9];
    const float* att2 = (const float*)d_in[10];
    const float* Wm3 = (const float*)d_in[11]; const float* bm3 = (const float*)d_in[12];
    const float* Ws3 = (const float*)d_in[13]; const float* bs3 = (const float*)d_in[14];
    const float* att3 = (const float*)d_in[15];
    const float* Wm4 = (const float*)d_in[16]; const float* bm4 = (const float*)d_in[17];
    const float* Ws4 = (const float*)d_in[18]; const float* bs4 = (const float*)d_in[19];
    const float* att4 = (const float*)d_in[20];
    const float* Wm5 = (const float*)d_in[21]; const float* bm5 = (const float*)d_in[22];
    const float* Ws5 = (const float*)d_in[23]; const float* bs5 = (const float*)d_in[24];
    const float* att5 = (const float*)d_in[25];
    const float* Wc  = (const float*)d_in[26]; const float* bc  = (const float*)d_in[27];

    __half *ymsg, *xh, *xl, *w16;
    float *yself, *bufA, *bufB, *bias;
    cudaGetSymbolAddress((void**)&ymsg,  g_ymsg);
    cudaGetSymbolAddress((void**)&yself, g_yself);
    cudaGetSymbolAddress((void**)&bufA,  g_bufA);
    cudaGetSymbolAddress((void**)&bufB,  g_bufB);
    cudaGetSymbolAddress((void**)&xh,    g_xh);
    cudaGetSymbolAddress((void**)&xl,    g_xl);
    cudaGetSymbolAddress((void**)&w16,   g_w16);
    cudaGetSymbolAddress((void**)&bias,  g_bias);

    const int SM128 = (2 * 64 * 136 + 128 * 136) * 2 + 1024;   // 70,656 B
    const int SM64  = (2 * 64 * 72  + 128 * 72)  * 2 + 1024;   // 37,888 B
    cudaFuncSetAttribute(gemm_mma<128, 128>, cudaFuncAttributeMaxDynamicSharedMemorySize, SM128);
    cudaFuncSetAttribute(gemm_mma<128, 64>,  cudaFuncAttributeMaxDynamicSharedMemorySize, SM128);
    cudaFuncSetAttribute(gemm_mma<64, 64>,   cudaFuncAttributeMaxDynamicSharedMemorySize, SM64);

    const int WTOT = 2 * 1152 * 128 + 1152 * 64;
    convert_w_all<<<(WTOT + 255) / 256, 256>>>(Wm2, bm2, Ws2, bs2,
                                               Wm3, bm3, Ws3, bs3,
                                               Wm4, bm4, Ws4, bs4, w16, bias);

    // Layer 1
    alpha1<<<NUMNODES / 32, 256>>>(nodes, Wm1, bm1, att1);
    out1<<<NUMNODES / 32, 256>>>(nodes, Wm1, bm1, Ws1, bs1, xh, xl);

    const dim3 GG(NUMNODES / 64, 9);

    // Layer 2: K=128, C=128
    gemm_mma<128, 128><<<GG, 128, SM128>>>(xh, xl, w16 + 0 * WSLOT,
                                           bias + 0 * 1152, att2, ymsg, yself);
    agg2h<128, 8, true, true, false><<<NUMNODES / 8, 256>>>(ymsg, yself, nullptr, xh, xl);

    // Layer 3: K=128, C=64
    gemm_mma<128, 64><<<GG, 128, SM128>>>(xh, xl, w16 + 1 * WSLOT,
                                          bias + 1 * 1152, att3, ymsg, yself);
    agg2h<64, 16, true, true, false><<<NUMNODES / 16, 256>>>(ymsg, yself, nullptr, xh, xl);

    // Layer 4: K=64, C=64
    gemm_mma<64, 64><<<GG, 128, SM64>>>(xh, xl, w16 + 2 * WSLOT,
                                        bias + 2 * 1152, att4, ymsg, yself);
    agg2h<64, 16, true, false, true><<<NUMNODES / 16, 256>>>(ymsg, yself, bufB, nullptr, nullptr);

    // Layer 5 (small, fp32) — reuse yself as stride-64 scratch
    msg5<<<NUMNODES / 8, 256>>>(bufB, Wm5, bm5, Ws5, bs5, att5, yself);
    agg5<<<NUMNODES / 32, 256>>>(yself, bufA);

    final_k<<<1, 1024>>>(bufA, Wc, bc, (float*)d_out, out_size);
}